// round 3
// baseline (speedup 1.0000x reference)
#include <cuda_runtime.h>
#include <math.h>

// Problem constants (fixed by the benchmark)
#define BB      8
#define NN      3072
#define T_OUT   128
#define C_IN    32
#define D_EMB   8
#define C_OUTD  64
#define NBUCK   (BB * C_IN)     // 256 buckets (b, channel)
#define NPTS    (BB * NN)       // 24576 points
#define BIGV    1e10f

// ---------------- scratch (static device globals; no allocation) -------------
__device__ int    g_counts[NBUCK];
__device__ int    g_cursor[NBUCK];
__device__ int    g_offsets[NBUCK + 1];
__device__ float  g_bt[NPTS];       // bucketed t
__device__ float  g_bv[NPTS];       // bucketed v
__device__ float  g_bp[NPTS];       // bucketed padding flag (0/1)
__device__ float4 g_acc[NBUCK * T_OUT];  // scanned (S0=Z, S1=Σdw·t, S2=Σdw·v, cnt)

// ---------------- K0: zero counters ------------------------------------------
__global__ void k0_zero() {
    int i = threadIdx.x;
    if (i < NBUCK) { g_counts[i] = 0; g_cursor[i] = 0; }
}

// ---------------- K1: histogram of (b, channel) -------------------------------
__global__ void k1_hist(const float* __restrict__ x) {
    int i = blockIdx.x * blockDim.x + threadIdx.x;
    if (i >= NPTS) return;
    int b = i / NN;
    int f = (int)x[i * 3 + 0];
    atomicAdd(&g_counts[b * C_IN + f], 1);
}

// ---------------- K2: exclusive prefix over 256 counts ------------------------
__global__ void k2_prefix() {
    __shared__ int s[NBUCK];
    int tid = threadIdx.x;
    s[tid] = g_counts[tid];
    __syncthreads();
    for (int d = 1; d < NBUCK; d <<= 1) {
        int v = (tid >= d) ? s[tid - d] : 0;
        __syncthreads();
        s[tid] += v;
        __syncthreads();
    }
    g_offsets[tid + 1] = s[tid];
    if (tid == 0) g_offsets[0] = 0;
}

// ---------------- K3: scatter points into (b,channel) buckets -----------------
__global__ void k3_scatter(const float* __restrict__ x) {
    int i = blockIdx.x * blockDim.x + threadIdx.x;
    if (i >= NPTS) return;
    int b = i / NN;
    float ff = x[i * 3 + 0];
    float vv = x[i * 3 + 1];
    float tt = x[i * 3 + 2];
    int f = (int)ff;
    int bkt = b * C_IN + f;
    int pos = g_offsets[bkt] + atomicAdd(&g_cursor[bkt], 1);
    g_bt[pos] = tt;
    g_bv[pos] = vv;
    g_bp[pos] = (ff != 0.f || vv != 0.f || tt != 0.f) ? 1.f : 0.f;
}

// ---------------- K4: per-bucket inv_density + scatter to tau + scan ----------
__global__ void k4_bucket(const float* __restrict__ outpos,
                          const float* __restrict__ ksp) {
    const int BT = 256;                 // block threads
    int bkt = blockIdx.x;
    int tid = threadIdx.x;
    int off = g_offsets[bkt];
    int k   = g_offsets[bkt + 1] - off;
    float ks = ksp[0];

    __shared__ float  spos[T_OUT];
    __shared__ float4 sacc[T_OUT];
    __shared__ float  st[1024];

    if (tid < T_OUT) {
        spos[tid] = outpos[tid];
        sacc[tid] = make_float4(0.f, 0.f, 0.f, 0.f);
    }
    __syncthreads();

    for (int p0 = 0; p0 < k; p0 += BT) {
        int p = p0 + tid;
        bool act = (p < k);
        float tp = act ? g_bt[off + p] : 0.f;
        float mind = BIGV;

        for (int ts = 0; ts < k; ts += 1024) {
            int tl = min(1024, k - ts);
            for (int j = tid; j < tl; j += BT) st[j] = g_bt[off + ts + j];
            __syncthreads();
            if (act) {
                for (int j = 0; j < tl; j++) {
                    float d = fabsf(tp - st[j]);
                    if (d > 0.f) mind = fminf(mind, d);   // pd!=0 excludes self / equal t
                }
            }
            __syncthreads();
        }

        if (act && g_bp[off + p] != 0.f) {
            float dw = powf(mind, ks);
            // lower_bound: smallest tau with pos[tau] >= tp  (causal: tp <= pos)
            int lo = 0, hi = T_OUT;
            while (lo < hi) {
                int mid = (lo + hi) >> 1;
                if (spos[mid] < tp) lo = mid + 1; else hi = mid;
            }
            if (lo < T_OUT) {
                float vp = g_bv[off + p];
                atomicAdd(&sacc[lo].x, dw);
                atomicAdd(&sacc[lo].y, dw * tp);
                atomicAdd(&sacc[lo].z, dw * vp);
                atomicAdd(&sacc[lo].w, 1.f);
            }
        }
        __syncthreads();
    }

    // inclusive scan over tau (suffix-contribution -> prefix sum)
    for (int d = 1; d < T_OUT; d <<= 1) {
        float4 v = make_float4(0.f, 0.f, 0.f, 0.f);
        if (tid < T_OUT && tid >= d) v = sacc[tid - d];
        __syncthreads();
        if (tid < T_OUT) {
            sacc[tid].x += v.x; sacc[tid].y += v.y;
            sacc[tid].z += v.z; sacc[tid].w += v.w;
        }
        __syncthreads();
    }
    if (tid < T_OUT) g_acc[bkt * T_OUT + tid] = sacc[tid];
}

// ---------------- K5: epilogue — fe + GEMV with W_lin --------------------------
__global__ void k5_out(const float* __restrict__ outpos,
                       const float* __restrict__ Wd,  const float* __restrict__ bd,
                       const float* __restrict__ emb, const float* __restrict__ Wv,
                       const float* __restrict__ bv,  const float* __restrict__ Wl,
                       const float* __restrict__ bl,  float* __restrict__ out) {
    int tau = blockIdx.x;     // 0..127
    int b   = blockIdx.y;     // 0..7
    int tid = threadIdx.x;    // 256 threads

    __shared__ float fe[C_IN * D_EMB];   // 256
    __shared__ float sWd[D_EMB], sWv[D_EMB], sK[D_EMB];
    __shared__ float smax;

    if (tid < D_EMB) {
        sWd[tid] = Wd[tid];
        sWv[tid] = Wv[tid];
        sK[tid]  = bd[tid] + bv[tid];
    }
    if (tid == 0) {
        float m = outpos[0];
        for (int i = 1; i < T_OUT; i++) m = fmaxf(m, outpos[i]);
        smax = m;
    }
    __syncthreads();

    int c = tid >> 3;         // channel 0..31
    int d = tid & 7;          // emb dim 0..7
    float4 a = g_acc[(b * C_IN + c) * T_OUT + tau];
    float S0 = a.x, S1 = a.y, S2 = a.z, cnt = a.w;
    float pt = outpos[tau];
    float A  = (S1 - pt * S0) / smax;
    float num = A * sWd[d] + S0 * (sK[d] + emb[c * D_EMB + d]) + S2 * sWv[d];
    fe[tid] = num / (S0 + 1e-10f) / (cnt + 1e-10f);
    __syncthreads();

    if (tid < C_OUTD) {
        float acc = bl[tid];
        const float* w = Wl + tid * (C_IN * D_EMB);
        #pragma unroll 8
        for (int j = 0; j < C_IN * D_EMB; j++) acc += fe[j] * w[j];
        out[(b * C_OUTD + tid) * T_OUT + tau] = acc;  // (B, C_OUT, T) layout
    }
}

// ---------------- launch ------------------------------------------------------
extern "C" void kernel_launch(void* const* d_in, const int* in_sizes, int n_in,
                              void* d_out, int out_size) {
    const float* x    = (const float*)d_in[0];  // (B,N,3)
    const float* pos  = (const float*)d_in[1];  // (T_OUT,)
    const float* Wd   = (const float*)d_in[2];  // (D_EMB,)
    const float* bd   = (const float*)d_in[3];  // (D_EMB,)
    const float* emb  = (const float*)d_in[4];  // (C_IN+1, D_EMB)
    const float* Wv   = (const float*)d_in[5];  // (D_EMB,)
    const float* bvv  = (const float*)d_in[6];  // (D_EMB,)
    const float* Wl   = (const float*)d_in[7];  // (C_OUT, D_EMB*C_IN)
    const float* bl   = (const float*)d_in[8];  // (C_OUT,)
    const float* ks   = (const float*)d_in[9];  // scalar
    float* out = (float*)d_out;

    k0_zero<<<1, 256>>>();
    k1_hist<<<(NPTS + 255) / 256, 256>>>(x);
    k2_prefix<<<1, NBUCK>>>();
    k3_scatter<<<(NPTS + 255) / 256, 256>>>(x);
    k4_bucket<<<NBUCK, 256>>>(pos, ks);
    dim3 g5(T_OUT, BB);
    k5_out<<<g5, 256>>>(pos, Wd, bd, emb, Wv, bvv, Wl, bl, out);
}

// round 4
// speedup vs baseline: 1.1627x; 1.1627x over previous
#include <cuda_runtime.h>
#include <math.h>

// Problem constants (fixed by the benchmark)
#define BB      8
#define NN      3072
#define T_OUT   128
#define C_IN    32
#define D_EMB   8
#define C_OUTD  64
#define NBUCK   (BB * C_IN)     // 256 buckets (b, channel)
#define BIGV    1e10f

// scanned per-(b,c,tau) sums: (S0=Z, S1=sum dw*t, S2=sum dw*v, cnt)
__device__ float4 g_acc[NBUCK * T_OUT];

// ---------------- Kernel A: fused gather + inv_density + tau scatter + scan ---
// One block per (b, channel). Re-scan row x[b], keep points with f==c in shared.
__global__ __launch_bounds__(256) void kA_bucket(const float* __restrict__ x,
                                                 const float* __restrict__ outpos,
                                                 const float* __restrict__ ksp) {
    const int bkt = blockIdx.x;          // 0..255
    const int b   = bkt >> 5;            // batch
    const int c   = bkt & 31;            // channel
    const int tid = threadIdx.x;         // 256 threads

    __shared__ float  st[NN];            // t of matching points (worst case all N)
    __shared__ float  sv[NN];            // v of matching points
    __shared__ unsigned char spd[NN];    // padding flag
    __shared__ float  spos[T_OUT];
    __shared__ float4 sacc[T_OUT];
    __shared__ int    scnt;

    if (tid == 0) scnt = 0;
    if (tid < T_OUT) {
        spos[tid] = outpos[tid];
        sacc[tid] = make_float4(0.f, 0.f, 0.f, 0.f);
    }
    __syncthreads();

    // Gather this block's channel points from x[b] (L2-resident after 1st touch).
    const float* xb = x + (size_t)b * NN * 3;
    for (int i = tid; i < NN; i += 256) {
        float ff = xb[i * 3 + 0];
        if ((int)ff == c) {
            float vv = xb[i * 3 + 1];
            float tt = xb[i * 3 + 2];
            int p = atomicAdd(&scnt, 1);           // shared atomic, order irrelevant
            st[p]  = tt;
            sv[p]  = vv;
            spd[p] = (ff != 0.f || vv != 0.f || tt != 0.f) ? 1 : 0;
        }
    }
    __syncthreads();

    const int k = scnt;
    const float ks = ksp[0];

    // Pairwise min |t_p - t_j| over same-(b,channel) points (pd!=0 excludes
    // self and exact duplicates), then dw scatter into first causal tau bucket.
    for (int p = tid; p < k; p += 256) {
        float tp = st[p];
        float mind = BIGV;
        for (int j = 0; j < k; j++) {
            float d = fabsf(tp - st[j]);
            if (d > 0.f) mind = fminf(mind, d);
        }
        if (spd[p]) {
            float dw = powf(mind, ks);
            // lower_bound: smallest tau with pos[tau] >= tp  (causal: tp <= pos)
            int lo = 0, hi = T_OUT;
            while (lo < hi) {
                int mid = (lo + hi) >> 1;
                if (spos[mid] < tp) lo = mid + 1; else hi = mid;
            }
            if (lo < T_OUT) {
                float vp = sv[p];
                atomicAdd(&sacc[lo].x, dw);
                atomicAdd(&sacc[lo].y, dw * tp);
                atomicAdd(&sacc[lo].z, dw * vp);
                atomicAdd(&sacc[lo].w, 1.f);
            }
        }
    }
    __syncthreads();

    // Inclusive scan over tau (suffix-contribution -> prefix sum).
    for (int d = 1; d < T_OUT; d <<= 1) {
        float4 v = make_float4(0.f, 0.f, 0.f, 0.f);
        if (tid < T_OUT && tid >= d) v = sacc[tid - d];
        __syncthreads();
        if (tid < T_OUT) {
            sacc[tid].x += v.x; sacc[tid].y += v.y;
            sacc[tid].z += v.z; sacc[tid].w += v.w;
        }
        __syncthreads();
    }
    if (tid < T_OUT) g_acc[bkt * T_OUT + tid] = sacc[tid];
}

// ---------------- Kernel B: epilogue — fe + GEMV with W_lin --------------------
__global__ __launch_bounds__(256) void kB_out(const float* __restrict__ outpos,
                       const float* __restrict__ Wd,  const float* __restrict__ bd,
                       const float* __restrict__ emb, const float* __restrict__ Wv,
                       const float* __restrict__ bv,  const float* __restrict__ Wl,
                       const float* __restrict__ bl,  float* __restrict__ out) {
    int tau = blockIdx.x;     // 0..127
    int b   = blockIdx.y;     // 0..7
    int tid = threadIdx.x;    // 256 threads

    __shared__ float fe[C_IN * D_EMB];   // 256
    __shared__ float sWd[D_EMB], sWv[D_EMB], sK[D_EMB];
    __shared__ float smax;

    if (tid < D_EMB) {
        sWd[tid] = Wd[tid];
        sWv[tid] = Wv[tid];
        sK[tid]  = bd[tid] + bv[tid];
    }
    if (tid == 0) {
        float m = outpos[0];
        for (int i = 1; i < T_OUT; i++) m = fmaxf(m, outpos[i]);
        smax = m;
    }
    __syncthreads();

    int c = tid >> 3;         // channel 0..31
    int d = tid & 7;          // emb dim 0..7
    float4 a = g_acc[(b * C_IN + c) * T_OUT + tau];
    float S0 = a.x, S1 = a.y, S2 = a.z, cnt = a.w;
    float pt = outpos[tau];
    float A  = (S1 - pt * S0) / smax;
    float num = A * sWd[d] + S0 * (sK[d] + emb[c * D_EMB + d]) + S2 * sWv[d];
    fe[tid] = num / (S0 + 1e-10f) / (cnt + 1e-10f);
    __syncthreads();

    if (tid < C_OUTD) {
        float acc = bl[tid];
        const float* w = Wl + tid * (C_IN * D_EMB);
        #pragma unroll 8
        for (int j = 0; j < C_IN * D_EMB; j++) acc += fe[j] * w[j];
        out[(b * C_OUTD + tid) * T_OUT + tau] = acc;  // (B, C_OUT, T) layout
    }
}

// ---------------- launch ------------------------------------------------------
extern "C" void kernel_launch(void* const* d_in, const int* in_sizes, int n_in,
                              void* d_out, int out_size) {
    const float* x    = (const float*)d_in[0];  // (B,N,3)
    const float* pos  = (const float*)d_in[1];  // (T_OUT,)
    const float* Wd   = (const float*)d_in[2];  // (D_EMB,)
    const float* bd   = (const float*)d_in[3];  // (D_EMB,)
    const float* emb  = (const float*)d_in[4];  // (C_IN+1, D_EMB)
    const float* Wv   = (const float*)d_in[5];  // (D_EMB,)
    const float* bvv  = (const float*)d_in[6];  // (D_EMB,)
    const float* Wl   = (const float*)d_in[7];  // (C_OUT, D_EMB*C_IN)
    const float* bl   = (const float*)d_in[8];  // (C_OUT,)
    const float* ks   = (const float*)d_in[9];  // scalar
    float* out = (float*)d_out;

    kA_bucket<<<NBUCK, 256>>>(x, pos, ks);
    dim3 gB(T_OUT, BB);
    kB_out<<<gB, 256>>>(pos, Wd, bd, emb, Wv, bvv, Wl, bl, out);
}

// round 5
// speedup vs baseline: 3.7528x; 3.2278x over previous
#include <cuda_runtime.h>
#include <math.h>

// Problem constants (fixed by the benchmark)
#define BB      8
#define NN      3072
#define T_OUT   128
#define C_IN    32
#define D_EMB   8
#define C_OUTD  64
#define NBUCK   (BB * C_IN)     // 256 buckets (b, channel)
#define BIGV    1e10f

// scanned per-(b,c,tau) sums: (S0=Z, S1=sum dw*t, S2=sum dw*v, cnt)
__device__ float4 g_acc[NBUCK * T_OUT];

// ---------------- Kernel A: fused gather + inv_density + tau scatter + scan ---
// One block per (b, channel). Re-scan row x[b], keep points with f==c in shared.
__global__ __launch_bounds__(256) void kA_bucket(const float* __restrict__ x,
                                                 const float* __restrict__ outpos,
                                                 const float* __restrict__ ksp) {
    const int bkt = blockIdx.x;          // 0..255
    const int b   = bkt >> 5;            // batch
    const int c   = bkt & 31;            // channel
    const int tid = threadIdx.x;         // 256 threads

    __shared__ float  st[NN];            // t of matching points (worst case all N)
    __shared__ float  sv[NN];            // v of matching points
    __shared__ unsigned char spd[NN];    // padding flag
    __shared__ float  spos[T_OUT];
    __shared__ float4 sacc[T_OUT];
    __shared__ int    scnt;

    if (tid == 0) scnt = 0;
    if (tid < T_OUT) {
        spos[tid] = outpos[tid];
        sacc[tid] = make_float4(0.f, 0.f, 0.f, 0.f);
    }
    __syncthreads();

    // Gather this block's channel points from x[b] (L2-resident after 1st touch).
    const float* xb = x + (size_t)b * NN * 3;
    for (int i = tid; i < NN; i += 256) {
        float ff = xb[i * 3 + 0];
        if ((int)ff == c) {
            float vv = xb[i * 3 + 1];
            float tt = xb[i * 3 + 2];
            int p = atomicAdd(&scnt, 1);           // shared atomic, order irrelevant
            st[p]  = tt;
            sv[p]  = vv;
            spd[p] = (ff != 0.f || vv != 0.f || tt != 0.f) ? 1 : 0;
        }
    }
    __syncthreads();

    const int k = scnt;
    const float ks = ksp[0];

    // Pairwise min |t_p - t_j| over same-(b,channel) points (pd!=0 excludes
    // self and exact duplicates), then dw scatter into first causal tau bucket.
    for (int p = tid; p < k; p += 256) {
        float tp = st[p];
        float mind = BIGV;
        for (int j = 0; j < k; j++) {
            float d = fabsf(tp - st[j]);
            if (d > 0.f) mind = fminf(mind, d);
        }
        if (spd[p]) {
            float dw = powf(mind, ks);
            // lower_bound: smallest tau with pos[tau] >= tp  (causal: tp <= pos)
            int lo = 0, hi = T_OUT;
            while (lo < hi) {
                int mid = (lo + hi) >> 1;
                if (spos[mid] < tp) lo = mid + 1; else hi = mid;
            }
            if (lo < T_OUT) {
                float vp = sv[p];
                atomicAdd(&sacc[lo].x, dw);
                atomicAdd(&sacc[lo].y, dw * tp);
                atomicAdd(&sacc[lo].z, dw * vp);
                atomicAdd(&sacc[lo].w, 1.f);
            }
        }
    }
    __syncthreads();

    // Inclusive scan over tau (suffix-contribution -> prefix sum).
    for (int d = 1; d < T_OUT; d <<= 1) {
        float4 v = make_float4(0.f, 0.f, 0.f, 0.f);
        if (tid < T_OUT && tid >= d) v = sacc[tid - d];
        __syncthreads();
        if (tid < T_OUT) {
            sacc[tid].x += v.x; sacc[tid].y += v.y;
            sacc[tid].z += v.z; sacc[tid].w += v.w;
        }
        __syncthreads();
    }
    if (tid < T_OUT) g_acc[bkt * T_OUT + tid] = sacc[tid];
}

// ---------------- Kernel B: factorized epilogue GEMM ---------------------------
// out[b,co,tau] = bl[co] + sum_c [ u1*P1 + u2*P2 + u3*P3 ](c,co)
//   P1[c,co] = sum_d Wd[d]*Wl[co,c*8+d]
//   P2[c,co] = sum_d (bd[d]+bv[d]+emb[c,d])*Wl[co,c*8+d]
//   P3[c,co] = sum_d Wv[d]*Wl[co,c*8+d]
//   u1 = r*A, u2 = r*S0, u3 = r*S2,  r = 1/((S0+eps)(cnt+eps)),
//   A  = (S1 - pos[tau]*S0)/max_pos
// 128 blocks x 8 rows(b,tau) each; 256 threads.
__global__ __launch_bounds__(256) void kB_gemm(const float* __restrict__ outpos,
                       const float* __restrict__ Wd,  const float* __restrict__ bd,
                       const float* __restrict__ emb, const float* __restrict__ Wv,
                       const float* __restrict__ bv,  const float* __restrict__ Wl,
                       const float* __restrict__ bl,  float* __restrict__ out) {
    const int tid = threadIdx.x;

    __shared__ float sP[96][C_OUTD];   // 24 KB, q = 3*c + term
    __shared__ float sU[8][96];        // 3 KB
    __shared__ float spos[T_OUT];
    __shared__ float smax;

    if (tid < T_OUT) spos[tid] = outpos[tid];
    __syncthreads();
    if (tid == 0) {
        float m = spos[0];
        for (int i = 1; i < T_OUT; i++) m = fmaxf(m, spos[i]);
        smax = m;
    }

    // Phase 1: contract d-dimension of Wl with the three d-vectors.
    for (int idx = tid; idx < C_IN * C_OUTD; idx += 256) {
        int c  = idx >> 6;       // 0..31
        int co = idx & 63;       // 0..63
        const float* w = Wl + co * (C_IN * D_EMB) + c * D_EMB;
        float p1 = 0.f, p2 = 0.f, p3 = 0.f;
        #pragma unroll
        for (int d = 0; d < D_EMB; d++) {
            float wv = w[d];
            p1 += Wd[d] * wv;
            p2 += (bd[d] + bv[d] + emb[c * D_EMB + d]) * wv;
            p3 += Wv[d] * wv;
        }
        sP[3 * c + 0][co] = p1;
        sP[3 * c + 1][co] = p2;
        sP[3 * c + 2][co] = p3;
    }
    __syncthreads();   // also publishes smax

    // Phase 2: per-row scalars u1,u2,u3 for 8 rows x 32 channels = 256 threads.
    {
        int r = tid >> 5;        // row slot 0..7
        int c = tid & 31;        // channel
        int row = blockIdx.x * 8 + r;     // row = b*T_OUT + tau
        int b   = row >> 7;
        int tau = row & 127;
        float4 a = g_acc[(b * C_IN + c) * T_OUT + tau];
        float r_ = 1.f / ((a.x + 1e-10f) * (a.w + 1e-10f));
        float A  = (a.y - spos[tau] * a.x) / smax;
        sU[r][3 * c + 0] = A   * r_;
        sU[r][3 * c + 1] = a.x * r_;
        sU[r][3 * c + 2] = a.z * r_;
    }
    __syncthreads();

    // Phase 3: (8 x 96) x (96 x 64) dot, all shared-resident.
    int co    = tid & 63;
    int rslot = tid >> 6;        // 0..3
    float blv = bl[co];
    for (int rr = rslot; rr < 8; rr += 4) {
        int row = blockIdx.x * 8 + rr;
        int b   = row >> 7;
        int tau = row & 127;
        float acc = blv;
        #pragma unroll
        for (int q = 0; q < 96; q++)
            acc += sU[rr][q] * sP[q][co];
        out[(b * C_OUTD + co) * T_OUT + tau] = acc;   // (B, C_OUT, T)
    }
}

// ---------------- launch ------------------------------------------------------
extern "C" void kernel_launch(void* const* d_in, const int* in_sizes, int n_in,
                              void* d_out, int out_size) {
    const float* x    = (const float*)d_in[0];  // (B,N,3)
    const float* pos  = (const float*)d_in[1];  // (T_OUT,)
    const float* Wd   = (const float*)d_in[2];  // (D_EMB,)
    const float* bd   = (const float*)d_in[3];  // (D_EMB,)
    const float* emb  = (const float*)d_in[4];  // (C_IN+1, D_EMB)
    const float* Wv   = (const float*)d_in[5];  // (D_EMB,)
    const float* bvv  = (const float*)d_in[6];  // (D_EMB,)
    const float* Wl   = (const float*)d_in[7];  // (C_OUT, D_EMB*C_IN)
    const float* bl   = (const float*)d_in[8];  // (C_OUT,)
    const float* ks   = (const float*)d_in[9];  // scalar
    float* out = (float*)d_out;

    kA_bucket<<<NBUCK, 256>>>(x, pos, ks);
    kB_gemm<<<(BB * T_OUT) / 8, 256>>>(pos, Wd, bd, emb, Wv, bvv, Wl, bl, out);
}

// round 6
// speedup vs baseline: 4.5719x; 1.2183x over previous
#include <cuda_runtime.h>
#include <math.h>

// Problem constants (fixed by the benchmark)
#define BB      8
#define NN      3072
#define T_OUT   128
#define C_IN    32
#define D_EMB   8
#define C_OUTD  64
#define NBUCK   (BB * C_IN)     // 256 buckets (b, channel)
#define BIGV    1e10f

// scanned per-(b,c,tau) sums: (S0=Z, S1=sum dw*t, S2=sum dw*v, cnt)
__device__ float4 g_acc[NBUCK * T_OUT];
// weight-only precompute: gP[q][co], q = 3*c + {0:Wd, 1:(bd+bv+emb[c]), 2:Wv}
__device__ float  g_P[96 * C_OUTD];
__device__ float  g_smax;

// ---------------- Kernel A: fused gather + inv_density + tau scatter + scan ---
// Blocks 0..255: one per (b, channel). Block 256: weight precompute (P, smax).
__global__ __launch_bounds__(256) void kA_bucket(const float* __restrict__ x,
                                                 const float* __restrict__ outpos,
                                                 const float* __restrict__ ksp,
                                                 const float* __restrict__ Wd,
                                                 const float* __restrict__ bd,
                                                 const float* __restrict__ emb,
                                                 const float* __restrict__ Wv,
                                                 const float* __restrict__ bv,
                                                 const float* __restrict__ Wl) {
    const int bkt = blockIdx.x;
    const int tid = threadIdx.x;         // 256 threads

    if (bkt == NBUCK) {
        // ---- weight-only precompute block ----
        __shared__ float sWd[D_EMB], sWv[D_EMB], sK[D_EMB];
        if (tid < D_EMB) {
            sWd[tid] = Wd[tid];
            sWv[tid] = Wv[tid];
            sK[tid]  = bd[tid] + bv[tid];
        }
        if (tid == 0) {
            float m = outpos[0];
            for (int i = 1; i < T_OUT; i++) m = fmaxf(m, outpos[i]);
            g_smax = m;
        }
        __syncthreads();
        // Each thread handles 8 (co,c) cells: 8 consecutive Wl floats each,
        // loaded as 2x float4 (coalesced across the warp: 32B/thread blocks).
        for (int cell = tid; cell < C_OUTD * C_IN; cell += 256) {
            int co = cell >> 5;          // 0..63
            int c  = cell & 31;          // 0..31
            const float4* w4 = (const float4*)(Wl + co * (C_IN * D_EMB) + c * D_EMB);
            float4 wa = w4[0], wb = w4[1];
            float we[8] = {wa.x, wa.y, wa.z, wa.w, wb.x, wb.y, wb.z, wb.w};
            float p1 = 0.f, p2 = 0.f, p3 = 0.f;
            #pragma unroll
            for (int d = 0; d < D_EMB; d++) {
                p1 += sWd[d] * we[d];
                p2 += (sK[d] + emb[c * D_EMB + d]) * we[d];
                p3 += sWv[d] * we[d];
            }
            g_P[(3 * c + 0) * C_OUTD + co] = p1;
            g_P[(3 * c + 1) * C_OUTD + co] = p2;
            g_P[(3 * c + 2) * C_OUTD + co] = p3;
        }
        return;
    }

    const int b = bkt >> 5;              // batch
    const int c = bkt & 31;              // channel

    __shared__ float  st[NN];            // t of matching points (worst case all N)
    __shared__ float  sv[NN];            // v of matching points
    __shared__ unsigned char spd[NN];    // padding flag
    __shared__ float  spos[T_OUT];
    __shared__ float4 sacc[T_OUT];
    __shared__ int    scnt;

    if (tid == 0) scnt = 0;
    if (tid < T_OUT) {
        spos[tid] = outpos[tid];
        sacc[tid] = make_float4(0.f, 0.f, 0.f, 0.f);
    }
    __syncthreads();

    // Gather this block's channel points from x[b] (L2-resident after 1st touch).
    const float* xb = x + (size_t)b * NN * 3;
    for (int i = tid; i < NN; i += 256) {
        float ff = xb[i * 3 + 0];
        if ((int)ff == c) {
            float vv = xb[i * 3 + 1];
            float tt = xb[i * 3 + 2];
            int p = atomicAdd(&scnt, 1);           // shared atomic, order irrelevant
            st[p]  = tt;
            sv[p]  = vv;
            spd[p] = (ff != 0.f || vv != 0.f || tt != 0.f) ? 1 : 0;
        }
    }
    __syncthreads();

    const int k = scnt;
    const float ks = ksp[0];

    // Pairwise min |t_p - t_j| over same-(b,channel) points (pd!=0 excludes
    // self and exact duplicates), then dw scatter into first causal tau bucket.
    for (int p = tid; p < k; p += 256) {
        float tp = st[p];
        float mind = BIGV;
        for (int j = 0; j < k; j++) {
            float d = fabsf(tp - st[j]);
            if (d > 0.f) mind = fminf(mind, d);
        }
        if (spd[p]) {
            float dw = powf(mind, ks);
            // lower_bound: smallest tau with pos[tau] >= tp  (causal: tp <= pos)
            int lo = 0, hi = T_OUT;
            while (lo < hi) {
                int mid = (lo + hi) >> 1;
                if (spos[mid] < tp) lo = mid + 1; else hi = mid;
            }
            if (lo < T_OUT) {
                float vp = sv[p];
                atomicAdd(&sacc[lo].x, dw);
                atomicAdd(&sacc[lo].y, dw * tp);
                atomicAdd(&sacc[lo].z, dw * vp);
                atomicAdd(&sacc[lo].w, 1.f);
            }
        }
    }
    __syncthreads();

    // Inclusive scan over tau (suffix-contribution -> prefix sum).
    for (int d = 1; d < T_OUT; d <<= 1) {
        float4 v = make_float4(0.f, 0.f, 0.f, 0.f);
        if (tid < T_OUT && tid >= d) v = sacc[tid - d];
        __syncthreads();
        if (tid < T_OUT) {
            sacc[tid].x += v.x; sacc[tid].y += v.y;
            sacc[tid].z += v.z; sacc[tid].w += v.w;
        }
        __syncthreads();
    }
    if (tid < T_OUT) g_acc[bkt * T_OUT + tid] = sacc[tid];
}

// ---------------- Kernel B: factorized epilogue GEMM ---------------------------
// out[b,co,tau] = bl[co] + sum_q sU[row][q] * P[q][co]
//   sU[row][3c+0] = r*A, [3c+1] = r*S0, [3c+2] = r*S2
//   r = 1/((S0+eps)(cnt+eps)),  A = (S1 - pos[tau]*S0)/max_pos
// 128 blocks x 8 rows(b,tau) each; 256 threads. P loaded from global (L2).
__global__ __launch_bounds__(256) void kB_gemm(const float* __restrict__ outpos,
                                               const float* __restrict__ bl,
                                               float* __restrict__ out) {
    const int tid = threadIdx.x;

    __shared__ float sP[96][C_OUTD];   // 24 KB
    __shared__ float sU[8][96];        // 3 KB
    __shared__ float spos[T_OUT];

    if (tid < T_OUT) spos[tid] = outpos[tid];

    // Phase 1: coalesced float4 load of precomputed P (24 KB, L2-resident).
    {
        const float4* src = (const float4*)g_P;
        float4* dst = (float4*)&sP[0][0];
        #pragma unroll
        for (int i = 0; i < (96 * C_OUTD / 4) / 256; i++)
            dst[tid + i * 256] = src[tid + i * 256];
    }
    __syncthreads();

    // Phase 2: per-row scalars u1,u2,u3 for 8 rows x 32 channels = 256 threads.
    {
        float smax = g_smax;
        int r = tid >> 5;        // row slot 0..7
        int c = tid & 31;        // channel
        int row = blockIdx.x * 8 + r;     // row = b*T_OUT + tau
        int b   = row >> 7;
        int tau = row & 127;
        float4 a = g_acc[(b * C_IN + c) * T_OUT + tau];
        float r_ = 1.f / ((a.x + 1e-10f) * (a.w + 1e-10f));
        float A  = (a.y - spos[tau] * a.x) / smax;
        sU[r][3 * c + 0] = A   * r_;
        sU[r][3 * c + 1] = a.x * r_;
        sU[r][3 * c + 2] = a.z * r_;
    }
    __syncthreads();

    // Phase 3: (8 x 96) x (96 x 64) dot, all shared-resident.
    int co    = tid & 63;
    int rslot = tid >> 6;        // 0..3
    float blv = bl[co];
    for (int rr = rslot; rr < 8; rr += 4) {
        int row = blockIdx.x * 8 + rr;
        int b   = row >> 7;
        int tau = row & 127;
        float acc = blv;
        #pragma unroll
        for (int q = 0; q < 96; q++)
            acc += sU[rr][q] * sP[q][co];
        out[(b * C_OUTD + co) * T_OUT + tau] = acc;   // (B, C_OUT, T)
    }
}

// ---------------- launch ------------------------------------------------------
extern "C" void kernel_launch(void* const* d_in, const int* in_sizes, int n_in,
                              void* d_out, int out_size) {
    const float* x    = (const float*)d_in[0];  // (B,N,3)
    const float* pos  = (const float*)d_in[1];  // (T_OUT,)
    const float* Wd   = (const float*)d_in[2];  // (D_EMB,)
    const float* bd   = (const float*)d_in[3];  // (D_EMB,)
    const float* emb  = (const float*)d_in[4];  // (C_IN+1, D_EMB)
    const float* Wv   = (const float*)d_in[5];  // (D_EMB,)
    const float* bvv  = (const float*)d_in[6];  // (D_EMB,)
    const float* Wl   = (const float*)d_in[7];  // (C_OUT, D_EMB*C_IN)
    const float* bl   = (const float*)d_in[8];  // (C_OUT,)
    const float* ks   = (const float*)d_in[9];  // scalar
    float* out = (float*)d_out;

    kA_bucket<<<NBUCK + 1, 256>>>(x, pos, ks, Wd, bd, emb, Wv, bvv, Wl);
    kB_gemm<<<(BB * T_OUT) / 8, 256>>>(pos, bl, out);
}